// round 14
// baseline (speedup 1.0000x reference)
#include <cuda_runtime.h>
#include <cuda_bf16.h>
#include <cstdint>

// Problem shape
#define NB 16
#define NQ 2048
#define NK 2048
#define ND 128
// Tiling
#define BQ 64
#define BK 64
#define NTH 128          // 4 warps; warp w owns q rows [w*16, w*16+16)

// smem row stride in u32 (bf16x2 pairs): 64 data + 4 pad = 272B/row
#define QS 68
#define SMEM_U32 (4 * 64 * QS)     // QHI,QLO,KHI,KLO : 69,632 B

// ---------------------------------------------------------------------------
// bf16 hi/lo split of a float pair: lower 16 bits = f0, upper = f1
// ---------------------------------------------------------------------------
__device__ __forceinline__ void split2(float f0, float f1,
                                       uint32_t& hi, uint32_t& lo) {
    __nv_bfloat162 h = __floats2bfloat162_rn(f0, f1);
    uint32_t hu = *(uint32_t*)&h;
    float r0 = f0 - __uint_as_float(hu << 16);
    float r1 = f1 - __uint_as_float(hu & 0xffff0000u);
    __nv_bfloat162 l = __floats2bfloat162_rn(r0, r1);
    lo = *(uint32_t*)&l;
    hi = hu;
}

// mma.sync m16n8k16 row.col f32 += bf16 * bf16 (sm_80+ baseline PTX)
#define MMA(C, a0, a1, a2, a3, b0, b1)                                        \
    asm volatile("mma.sync.aligned.m16n8k16.row.col.f32.bf16.bf16.f32 "       \
        "{%0,%1,%2,%3}, {%4,%5,%6,%7}, {%8,%9}, {%0,%1,%2,%3};"               \
        : "+f"((C)[0]), "+f"((C)[1]), "+f"((C)[2]), "+f"((C)[3])              \
        : "r"(a0), "r"(a1), "r"(a2), "r"(a3), "r"(b0), "r"(b1))

#define LDSM4(r0, r1, r2, r3, a)                                              \
    asm volatile("ldmatrix.sync.aligned.m8n8.x4.shared.b16 {%0,%1,%2,%3}, [%4];" \
        : "=r"(r0), "=r"(r1), "=r"(r2), "=r"(r3) : "r"(a))
#define LDSM4T(r0, r1, r2, r3, a)                                             \
    asm volatile("ldmatrix.sync.aligned.m8n8.x4.trans.shared.b16 {%0,%1,%2,%3}, [%4];" \
        : "=r"(r0), "=r"(r1), "=r"(r2), "=r"(r3) : "r"(a))

// ---------------------------------------------------------------------------
// JAX Threefry-2x32, key=[0,42]; partitionable: counter=(0,i), bits=x0^x1,
// keep <=> (bits>>9) < 5872026 (exact integer form of u<0.7f)
// ---------------------------------------------------------------------------
__device__ __forceinline__ uint32_t rotl32(uint32_t x, uint32_t r) {
    return __funnelshift_l(x, x, r);
}
__device__ __forceinline__ uint32_t keep_bit(uint32_t i) {
    const uint32_t ks1 = 42u;
    const uint32_t ks2 = 42u ^ 0x1BD11BDAu;
    uint32_t x0 = 0u, x1 = i + ks1;
#define TF_R(r) { x0 += x1; x1 = rotl32(x1, (r)); x1 ^= x0; }
    TF_R(13) TF_R(15) TF_R(26) TF_R(6)
    x0 += ks1; x1 += ks2 + 1u;
    TF_R(17) TF_R(29) TF_R(16) TF_R(24)
    x0 += ks2; x1 += 2u;
    TF_R(13) TF_R(15) TF_R(26) TF_R(6)
    x1 += ks1 + 3u;
    TF_R(17) TF_R(29) TF_R(16) TF_R(24)
    x0 += ks1; x1 += ks2 + 4u;
    TF_R(13) TF_R(15) TF_R(26) TF_R(6)
    x0 += ks2; x1 += 5u;
#undef TF_R
    return (((x0 ^ x1) >> 9) < 5872026u) ? 1u : 0u;
}

// ---------------------------------------------------------------------------
// Tensor-core flash attention: mma.sync bf16 hi/lo, ldmatrix fragment loads,
// V-frags via ldmatrix.trans from the K buffers (V == K tile),
// fixed-max softmax, threefry keep-bits hoisted before GEMM1,
// 2-way interleaved accumulator chains in both GEMMs.
// ---------------------------------------------------------------------------
__global__ void __launch_bounds__(NTH, 2)
attn_kernel(const float* __restrict__ x1, const float* __restrict__ x2,
            float* __restrict__ out) {
    extern __shared__ uint32_t smem[];
    uint32_t* QHI = smem;                 // [64][QS]
    uint32_t* QLO = QHI + 64 * QS;
    uint32_t* KHI = QLO + 64 * QS;        // [64][QS]  (K and V share this tile)
    uint32_t* KLO = KHI + 64 * QS;

    const int tid  = threadIdx.x;
    const int lane = tid & 31;
    const int wid  = tid >> 5;
    const int quad = lane & 3;
    const int rowq = lane >> 2;
    const int seg  = lane >> 3;
    const int r8   = lane & 7;
    const int b = blockIdx.y, q0 = blockIdx.x * BQ;

    const uint32_t aQHI = (uint32_t)__cvta_generic_to_shared(QHI);
    const uint32_t aQLO = (uint32_t)__cvta_generic_to_shared(QLO);
    const uint32_t aKHI = (uint32_t)__cvta_generic_to_shared(KHI);
    const uint32_t aKLO = (uint32_t)__cvta_generic_to_shared(KLO);

    const uint32_t offA  = (uint32_t)((wid * 16 + (seg & 1) * 8 + r8) * QS + (seg >> 1) * 4);
    const uint32_t offB1 = (uint32_t)(((seg >> 1) * 8 + r8) * QS + (seg & 1) * 4);
    const uint32_t offB2 = (uint32_t)(((seg & 1) * 8 + r8) * QS + (seg >> 1) * 4);

    // ---- convert Q once (scale 1.153 folded in)
    const float* gq = x1 + (size_t)(b * NQ + q0) * ND;
#pragma unroll
    for (int it = 0; it < 32; it++) {
        int idx = tid + it * NTH;
        int row = idx >> 6, cp = idx & 63;
        float2 v = *(const float2*)(gq + row * ND + 2 * cp);
        uint32_t hi, lo;
        split2(v.x * 1.153f, v.y * 1.153f, hi, lo);
        QHI[row * QS + cp] = hi;
        QLO[row * QS + cp] = lo;
    }

    float On[16][4];
#pragma unroll
    for (int dn = 0; dn < 16; dn++)
#pragma unroll
        for (int c = 0; c < 4; c++) On[dn][c] = 0.0f;
    float lp0 = 0.0f, lp1 = 0.0f;

    const uint32_t rb0 = (uint32_t)(b * NQ + q0 + wid * 16 + rowq) * (uint32_t)NK;
    const uint32_t rb1 = rb0 + 8u * (uint32_t)NK;
    const float* gk0 = x2 + (size_t)b * NK * ND;

    for (int kt = 0; kt < NK / BK; kt++) {
        __syncthreads();                  // prev tile's GEMMs done with K
        const float* gk = gk0 + (size_t)(kt * BK) * ND;

        // ---- convert K tile [64 kv][128 d] -> KHI/KLO (single pass; V reuses)
#pragma unroll
        for (int it = 0; it < 32; it++) {
            int idx = tid + it * NTH;
            int kr = idx >> 6, cp = idx & 63;
            float2 v = *(const float2*)(gk + kr * ND + 2 * cp);
            uint32_t hi, lo;
            split2(v.x, v.y, hi, lo);
            KHI[kr * QS + cp] = hi;
            KLO[kr * QS + cp] = lo;
        }
        __syncthreads();

        // ---- threefry keep bits for this tile (independent of S: fills
        //      GEMM1's MMA-stall shadow). Bit layout: 4*n + {00,01,10,11}.
        uint32_t km = 0u;
#pragma unroll
        for (int n = 0; n < 8; n++) {
            uint32_t kg = (uint32_t)(kt * BK + n * 8 + 2 * quad);
            km |= keep_bit(rb0 + kg)      << (4 * n);
            km |= keep_bit(rb0 + kg + 1u) << (4 * n + 1);
            km |= keep_bit(rb1 + kg)      << (4 * n + 2);
            km |= keep_bit(rb1 + kg + 1u) << (4 * n + 3);
        }

        // ---- GEMM1: C[8 ntiles][4] = Qs @ K^T; 2 interleaved chains per np
        float C[8][4];
#pragma unroll
        for (int n = 0; n < 8; n++)
#pragma unroll
            for (int c = 0; c < 4; c++) C[n][c] = 0.0f;

#pragma unroll
        for (int dc = 0; dc < 8; dc++) {
            uint32_t ah0, ah1, ah2, ah3, al0, al1, al2, al3;
            LDSM4(ah0, ah1, ah2, ah3, aQHI + (offA + dc * 8) * 4);
            LDSM4(al0, al1, al2, al3, aQLO + (offA + dc * 8) * 4);
#pragma unroll
            for (int np = 0; np < 4; np++) {
                uint32_t d1 = (offB1 + (uint32_t)(np * 16) * QS + dc * 8) * 4;
                uint32_t bh0, bh1, bh2, bh3, bl0, bl1, bl2, bl3;
                LDSM4(bh0, bh1, bh2, bh3, aKHI + d1);
                LDSM4(bl0, bl1, bl2, bl3, aKLO + d1);
                // interleave the two accumulator chains (in-order issue ILP)
                MMA(C[2 * np],     ah0, ah1, ah2, ah3, bh0, bh1);
                MMA(C[2 * np + 1], ah0, ah1, ah2, ah3, bh2, bh3);
                MMA(C[2 * np],     ah0, ah1, ah2, ah3, bl0, bl1);
                MMA(C[2 * np + 1], ah0, ah1, ah2, ah3, bl2, bl3);
                MMA(C[2 * np],     al0, al1, al2, al3, bh0, bh1);
                MMA(C[2 * np + 1], al0, al1, al2, al3, bh2, bh3);
            }
        }

        // ---- fixed-max softmax (exp + masked select), pack P into A-frags
        uint32_t phi[4][4], plo[4][4];
#pragma unroll
        for (int n = 0; n < 8; n++) {
            float e0 = __expf(C[n][0]);
            float e1 = __expf(C[n][1]);
            float e2 = __expf(C[n][2]);
            float e3 = __expf(C[n][3]);
            lp0 += e0 + e1;               // unmasked denominator
            lp1 += e2 + e3;
            uint32_t mb = km >> (4 * n);
            float p00 = (mb & 1u)        ? e0 : 0.0f;
            float p01 = ((mb >> 1) & 1u) ? e1 : 0.0f;
            float p10 = ((mb >> 2) & 1u) ? e2 : 0.0f;
            float p11 = ((mb >> 3) & 1u) ? e3 : 0.0f;
            int kc = n >> 1;
            if ((n & 1) == 0) {
                split2(p00, p01, phi[kc][0], plo[kc][0]);
                split2(p10, p11, phi[kc][1], plo[kc][1]);
            } else {
                split2(p00, p01, phi[kc][2], plo[kc][2]);
                split2(p10, p11, phi[kc][3], plo[kc][3]);
            }
        }

        // ---- GEMM2: On += P @ V; 2 interleaved chains per dnp
#pragma unroll
        for (int kc = 0; kc < 4; kc++) {
#pragma unroll
            for (int dnp = 0; dnp < 8; dnp++) {
                uint32_t d2 = (offB2 + (uint32_t)(kc * 16) * QS + dnp * 8) * 4;
                uint32_t vh0, vh1, vh2, vh3, vl0, vl1, vl2, vl3;
                LDSM4T(vh0, vh1, vh2, vh3, aKHI + d2);
                LDSM4T(vl0, vl1, vl2, vl3, aKLO + d2);
                MMA(On[2 * dnp],     phi[kc][0], phi[kc][1], phi[kc][2], phi[kc][3], vh0, vh1);
                MMA(On[2 * dnp + 1], phi[kc][0], phi[kc][1], phi[kc][2], phi[kc][3], vh2, vh3);
                MMA(On[2 * dnp],     phi[kc][0], phi[kc][1], phi[kc][2], phi[kc][3], vl0, vl1);
                MMA(On[2 * dnp + 1], phi[kc][0], phi[kc][1], phi[kc][2], phi[kc][3], vl2, vl3);
                MMA(On[2 * dnp],     plo[kc][0], plo[kc][1], plo[kc][2], plo[kc][3], vh0, vh1);
                MMA(On[2 * dnp + 1], plo[kc][0], plo[kc][1], plo[kc][2], plo[kc][3], vh2, vh3);
            }
        }
    }

    // ---- epilogue: reduce l over quad lanes, normalize, store
    lp0 += __shfl_xor_sync(0xffffffffu, lp0, 1);
    lp0 += __shfl_xor_sync(0xffffffffu, lp0, 2);
    lp1 += __shfl_xor_sync(0xffffffffu, lp1, 1);
    lp1 += __shfl_xor_sync(0xffffffffu, lp1, 2);
    float inv0 = 1.0f / (0.7f * lp0);
    float inv1 = 1.0f / (0.7f * lp1);

    float* g0 = out + (size_t)(b * NQ + q0 + wid * 16 + rowq) * ND + 2 * quad;
    float* g1 = g0 + 8 * ND;
#pragma unroll
    for (int dn = 0; dn < 16; dn++) {
        float2 s0; s0.x = On[dn][0] * inv0; s0.y = On[dn][1] * inv0;
        float2 s1; s1.x = On[dn][2] * inv1; s1.y = On[dn][3] * inv1;
        *(float2*)(g0 + dn * 8) = s0;
        *(float2*)(g1 + dn * 8) = s1;
    }
}

// ---------------------------------------------------------------------------
extern "C" void kernel_launch(void* const* d_in, const int* in_sizes, int n_in,
                              void* d_out, int out_size) {
    const float* x1 = (const float*)d_in[0];
    const float* x2 = (const float*)d_in[1];
    float* out = (float*)d_out;

    size_t smem = (size_t)SMEM_U32 * 4;   // 69,632 B
    cudaFuncSetAttribute(attn_kernel,
                         cudaFuncAttributeMaxDynamicSharedMemorySize, (int)smem);
    dim3 grid(NQ / BQ, NB);
    attn_kernel<<<grid, NTH, smem>>>(x1, x2, out);
}

// round 15
// speedup vs baseline: 1.0880x; 1.0880x over previous
#include <cuda_runtime.h>
#include <cuda_bf16.h>
#include <cstdint>

// Problem shape
#define NB 16
#define NQ 2048
#define NK 2048
#define ND 128
// Tiling
#define BQ 64
#define BK 64
#define NTH 256          // 8 warps; warp w: m-tile = w&3, half = w>>2

// smem strides in u32 (bf16x2 pairs)
#define QS 68            // Q/K rows: 64 data + 4 pad (272B: conflict-free ldmatrix)
#define PS 36            // P rows: 32 data + 4 pad (144B)
// u32 totals: Q 2*64*68, K 2*64*68, P 2*64*36, sL 128
#define SMEM_U32 (4 * 64 * QS + 2 * 64 * PS + 128)   // 22,144 u32 = 88,576 B

// ---------------------------------------------------------------------------
__device__ __forceinline__ void split2(float f0, float f1,
                                       uint32_t& hi, uint32_t& lo) {
    __nv_bfloat162 h = __floats2bfloat162_rn(f0, f1);
    uint32_t hu = *(uint32_t*)&h;
    float r0 = f0 - __uint_as_float(hu << 16);
    float r1 = f1 - __uint_as_float(hu & 0xffff0000u);
    __nv_bfloat162 l = __floats2bfloat162_rn(r0, r1);
    lo = *(uint32_t*)&l;
    hi = hu;
}

#define MMA(C, a0, a1, a2, a3, b0, b1)                                        \
    asm volatile("mma.sync.aligned.m16n8k16.row.col.f32.bf16.bf16.f32 "       \
        "{%0,%1,%2,%3}, {%4,%5,%6,%7}, {%8,%9}, {%0,%1,%2,%3};"               \
        : "+f"((C)[0]), "+f"((C)[1]), "+f"((C)[2]), "+f"((C)[3])              \
        : "r"(a0), "r"(a1), "r"(a2), "r"(a3), "r"(b0), "r"(b1))

#define LDSM4(r0, r1, r2, r3, a)                                              \
    asm volatile("ldmatrix.sync.aligned.m8n8.x4.shared.b16 {%0,%1,%2,%3}, [%4];" \
        : "=r"(r0), "=r"(r1), "=r"(r2), "=r"(r3) : "r"(a))
#define LDSM4T(r0, r1, r2, r3, a)                                             \
    asm volatile("ldmatrix.sync.aligned.m8n8.x4.trans.shared.b16 {%0,%1,%2,%3}, [%4];" \
        : "=r"(r0), "=r"(r1), "=r"(r2), "=r"(r3) : "r"(a))

// ---------------------------------------------------------------------------
// JAX Threefry-2x32, key=[0,42]; partitionable: counter=(0,i), bits=x0^x1,
// keep <=> (bits>>9) < 5872026 (exact integer form of u<0.7f)
// ---------------------------------------------------------------------------
__device__ __forceinline__ uint32_t rotl32(uint32_t x, uint32_t r) {
    return __funnelshift_l(x, x, r);
}
__device__ __forceinline__ uint32_t keep_bit(uint32_t i) {
    const uint32_t ks1 = 42u;
    const uint32_t ks2 = 42u ^ 0x1BD11BDAu;
    uint32_t x0 = 0u, x1 = i + ks1;
#define TF_R(r) { x0 += x1; x1 = rotl32(x1, (r)); x1 ^= x0; }
    TF_R(13) TF_R(15) TF_R(26) TF_R(6)
    x0 += ks1; x1 += ks2 + 1u;
    TF_R(17) TF_R(29) TF_R(16) TF_R(24)
    x0 += ks2; x1 += 2u;
    TF_R(13) TF_R(15) TF_R(26) TF_R(6)
    x1 += ks1 + 3u;
    TF_R(17) TF_R(29) TF_R(16) TF_R(24)
    x0 += ks1; x1 += ks2 + 4u;
    TF_R(13) TF_R(15) TF_R(26) TF_R(6)
    x0 += ks2; x1 += 5u;
#undef TF_R
    return (((x0 ^ x1) >> 9) < 5872026u) ? 1u : 0u;
}

// ---------------------------------------------------------------------------
// Tensor-core flash attention, 8-warp work-split:
//   GEMM1: warp (m, nh) computes C[4 n8-tiles], dropout, writes P to smem.
//   GEMM2: warp (m, dh) computes On[8 n8-tiles] over its d-half, P via ldmatrix.
// Fixed-max softmax, inline threefry, V-frags from K buffers (trans).
// ---------------------------------------------------------------------------
__global__ void __launch_bounds__(NTH, 2)
attn_kernel(const float* __restrict__ x1, const float* __restrict__ x2,
            float* __restrict__ out) {
    extern __shared__ uint32_t smem[];
    uint32_t* QHI = smem;                 // [64][QS]
    uint32_t* QLO = QHI + 64 * QS;
    uint32_t* KHI = QLO + 64 * QS;        // [64][QS]  (K and V share this tile)
    uint32_t* KLO = KHI + 64 * QS;
    uint32_t* PHI = KLO + 64 * QS;        // [64][PS]
    uint32_t* PLO = PHI + 64 * PS;
    float*    sL  = (float*)(PLO + 64 * PS);   // [2][64] l-half partials

    const int tid  = threadIdx.x;
    const int lane = tid & 31;
    const int wid  = tid >> 5;
    const int quad = lane & 3;
    const int rowq = lane >> 2;
    const int seg  = lane >> 3;
    const int r8   = lane & 7;
    const int m    = wid & 3;             // m-tile (q rows m*16..m*16+15)
    const int h    = wid >> 2;            // n-half (GEMM1) / d-half (GEMM2)
    const int b = blockIdx.y, q0 = blockIdx.x * BQ;

    const uint32_t aQHI = (uint32_t)__cvta_generic_to_shared(QHI);
    const uint32_t aQLO = (uint32_t)__cvta_generic_to_shared(QLO);
    const uint32_t aKHI = (uint32_t)__cvta_generic_to_shared(KHI);
    const uint32_t aKLO = (uint32_t)__cvta_generic_to_shared(KLO);
    const uint32_t aPHI = (uint32_t)__cvta_generic_to_shared(PHI);
    const uint32_t aPLO = (uint32_t)__cvta_generic_to_shared(PLO);

    // lane offsets (u32 units)
    const uint32_t offA  = (uint32_t)((m * 16 + (seg & 1) * 8 + r8) * QS + (seg >> 1) * 4);
    const uint32_t offB1 = (uint32_t)((h * 32 + (seg >> 1) * 8 + r8) * QS + (seg & 1) * 4);
    const uint32_t offB2 = (uint32_t)(((seg & 1) * 8 + r8) * QS + (seg >> 1) * 4 + h * 32);
    const uint32_t offPA = (uint32_t)((m * 16 + (seg & 1) * 8 + r8) * PS + (seg >> 1) * 4);

    // ---- convert Q once (scale 1.153 folded in)
    const float* gq = x1 + (size_t)(b * NQ + q0) * ND;
#pragma unroll
    for (int it = 0; it < 16; it++) {
        int idx = tid + it * NTH;
        int row = idx >> 6, cp = idx & 63;
        float2 v = *(const float2*)(gq + row * ND + 2 * cp);
        uint32_t hi, lo;
        split2(v.x * 1.153f, v.y * 1.153f, hi, lo);
        QHI[row * QS + cp] = hi;
        QLO[row * QS + cp] = lo;
    }

    float On[8][4];                       // GEMM2: d-half h, 8 n8-tiles
#pragma unroll
    for (int dn = 0; dn < 8; dn++)
#pragma unroll
        for (int c = 0; c < 4; c++) On[dn][c] = 0.0f;
    float lp0 = 0.0f, lp1 = 0.0f;         // l partials (rows m*16+rowq, +8) over n-half

    const uint32_t rb0 = (uint32_t)(b * NQ + q0 + m * 16 + rowq) * (uint32_t)NK;
    const uint32_t rb1 = rb0 + 8u * (uint32_t)NK;
    const float* gk0 = x2 + (size_t)b * NK * ND;

    for (int kt = 0; kt < NK / BK; kt++) {
        __syncthreads();                  // prev GEMM2 done with K and P
        const float* gk = gk0 + (size_t)(kt * BK) * ND;

        // ---- convert K tile [64 kv][128 d] (single pass; V reuses)
#pragma unroll
        for (int it = 0; it < 16; it++) {
            int idx = tid + it * NTH;
            int kr = idx >> 6, cp = idx & 63;
            float2 v = *(const float2*)(gk + kr * ND + 2 * cp);
            uint32_t hi, lo;
            split2(v.x, v.y, hi, lo);
            KHI[kr * QS + cp] = hi;
            KLO[kr * QS + cp] = lo;
        }
        __syncthreads();

        // ---- GEMM1: C[4 n8-tiles][4] for (m, n-half h)
        float C[4][4];
#pragma unroll
        for (int n = 0; n < 4; n++)
#pragma unroll
            for (int c = 0; c < 4; c++) C[n][c] = 0.0f;

#pragma unroll
        for (int dc = 0; dc < 8; dc++) {
            uint32_t ah0, ah1, ah2, ah3, al0, al1, al2, al3;
            LDSM4(ah0, ah1, ah2, ah3, aQHI + (offA + dc * 8) * 4);
            LDSM4(al0, al1, al2, al3, aQLO + (offA + dc * 8) * 4);
#pragma unroll
            for (int np = 0; np < 2; np++) {
                uint32_t d1 = (offB1 + (uint32_t)(np * 16) * QS + dc * 8) * 4;
                uint32_t bh0, bh1, bh2, bh3, bl0, bl1, bl2, bl3;
                LDSM4(bh0, bh1, bh2, bh3, aKHI + d1);
                LDSM4(bl0, bl1, bl2, bl3, aKLO + d1);
                MMA(C[2 * np],     ah0, ah1, ah2, ah3, bh0, bh1);
                MMA(C[2 * np],     ah0, ah1, ah2, ah3, bl0, bl1);
                MMA(C[2 * np],     al0, al1, al2, al3, bh0, bh1);
                MMA(C[2 * np + 1], ah0, ah1, ah2, ah3, bh2, bh3);
                MMA(C[2 * np + 1], ah0, ah1, ah2, ah3, bl2, bl3);
                MMA(C[2 * np + 1], al0, al1, al2, al3, bh2, bh3);
            }
        }

        // ---- fixed-max softmax + threefry dropout; write P hi/lo to smem
#pragma unroll
        for (int n = 0; n < 4; n++) {
            uint32_t kg = (uint32_t)(kt * BK + h * 32 + n * 8 + 2 * quad);
            float e0 = __expf(C[n][0]);
            float e1 = __expf(C[n][1]);
            float e2 = __expf(C[n][2]);
            float e3 = __expf(C[n][3]);
            lp0 += e0 + e1;               // unmasked denominator (this n-half)
            lp1 += e2 + e3;
            float p00 = keep_bit(rb0 + kg)      ? e0 : 0.0f;
            float p01 = keep_bit(rb0 + kg + 1u) ? e1 : 0.0f;
            float p10 = keep_bit(rb1 + kg)      ? e2 : 0.0f;
            float p11 = keep_bit(rb1 + kg + 1u) ? e3 : 0.0f;
            uint32_t hi0, lo0, hi1, lo1;
            split2(p00, p01, hi0, lo0);
            split2(p10, p11, hi1, lo1);
            int colp = h * 16 + n * 4 + quad;
            int rA = (m * 16 + rowq) * PS + colp;
            int rB = (m * 16 + rowq + 8) * PS + colp;
            PHI[rA] = hi0; PLO[rA] = lo0;
            PHI[rB] = hi1; PLO[rB] = lo1;
        }
        __syncthreads();                  // P ready for all warps

        // ---- GEMM2: On += P @ V for (m, d-half h); P via ldmatrix
#pragma unroll
        for (int kc = 0; kc < 4; kc++) {
            uint32_t pa = (offPA + (uint32_t)(kc * 8)) * 4;
            uint32_t ph0, ph1, ph2, ph3, pl0, pl1, pl2, pl3;
            LDSM4(ph0, ph1, ph2, ph3, aPHI + pa);
            LDSM4(pl0, pl1, pl2, pl3, aPLO + pa);
#pragma unroll
            for (int dnp = 0; dnp < 4; dnp++) {
                uint32_t d2 = (offB2 + (uint32_t)(kc * 16) * QS + dnp * 8) * 4;
                uint32_t vh0, vh1, vh2, vh3, vl0, vl1, vl2, vl3;
                LDSM4T(vh0, vh1, vh2, vh3, aKHI + d2);
                LDSM4T(vl0, vl1, vl2, vl3, aKLO + d2);
                MMA(On[2 * dnp],     ph0, ph1, ph2, ph3, vh0, vh1);
                MMA(On[2 * dnp],     ph0, ph1, ph2, ph3, vl0, vl1);
                MMA(On[2 * dnp],     pl0, pl1, pl2, pl3, vh0, vh1);
                MMA(On[2 * dnp + 1], ph0, ph1, ph2, ph3, vh2, vh3);
                MMA(On[2 * dnp + 1], ph0, ph1, ph2, ph3, vl2, vl3);
                MMA(On[2 * dnp + 1], pl0, pl1, pl2, pl3, vh2, vh3);
            }
        }
    }

    // ---- epilogue: merge l halves, normalize, store
    lp0 += __shfl_xor_sync(0xffffffffu, lp0, 1);
    lp0 += __shfl_xor_sync(0xffffffffu, lp0, 2);
    lp1 += __shfl_xor_sync(0xffffffffu, lp1, 1);
    lp1 += __shfl_xor_sync(0xffffffffu, lp1, 2);
    __syncthreads();                      // GEMM2 done with smem (incl. sL area? sL separate)
    if (quad == 0) {
        sL[h * 64 + m * 16 + rowq]     = lp0;
        sL[h * 64 + m * 16 + rowq + 8] = lp1;
    }
    __syncthreads();
    float inv0 = 1.0f / (0.7f * (sL[m * 16 + rowq]     + sL[64 + m * 16 + rowq]));
    float inv1 = 1.0f / (0.7f * (sL[m * 16 + rowq + 8] + sL[64 + m * 16 + rowq + 8]));

    float* g0 = out + (size_t)(b * NQ + q0 + m * 16 + rowq) * ND + h * 64 + 2 * quad;
    float* g1 = g0 + 8 * ND;
#pragma unroll
    for (int dn = 0; dn < 8; dn++) {
        float2 s0; s0.x = On[dn][0] * inv0; s0.y = On[dn][1] * inv0;
        float2 s1; s1.x = On[dn][2] * inv1; s1.y = On[dn][3] * inv1;
        *(float2*)(g0 + dn * 8) = s0;
        *(float2*)(g1 + dn * 8) = s1;
    }
}

// ---------------------------------------------------------------------------
extern "C" void kernel_launch(void* const* d_in, const int* in_sizes, int n_in,
                              void* d_out, int out_size) {
    const float* x1 = (const float*)d_in[0];
    const float* x2 = (const float*)d_in[1];
    float* out = (float*)d_out;

    size_t smem = (size_t)SMEM_U32 * 4;   // 88,576 B
    cudaFuncSetAttribute(attn_kernel,
                         cudaFuncAttributeMaxDynamicSharedMemorySize, (int)smem);
    dim3 grid(NQ / BQ, NB);
    attn_kernel<<<grid, NTH, smem>>>(x1, x2, out);
}

// round 16
// speedup vs baseline: 1.2292x; 1.1297x over previous
#include <cuda_runtime.h>
#include <cuda_bf16.h>
#include <cstdint>

// Problem shape
#define NB 16
#define NQ 2048
#define NK 2048
#define ND 128
// Tiling
#define BQ 64
#define BK 64
#define NTH 256          // 2 groups x 4 warps; group g handles tiles kt%2==g

#define QS 68            // row stride in u32 (64 data pairs + 4 pad)
#define REG (64 * QS)    // one 64-row region in u32 (4352)
// smem u32: QHI,QLO + per-group KHI,KLO (2 groups) + sL(128)
#define SMEM_U32 (6 * REG + 128)   // 26,240 u32 = 104,960 B

// ---------------------------------------------------------------------------
__device__ __forceinline__ void split2(float f0, float f1,
                                       uint32_t& hi, uint32_t& lo) {
    __nv_bfloat162 h = __floats2bfloat162_rn(f0, f1);
    uint32_t hu = *(uint32_t*)&h;
    float r0 = f0 - __uint_as_float(hu << 16);
    float r1 = f1 - __uint_as_float(hu & 0xffff0000u);
    __nv_bfloat162 l = __floats2bfloat162_rn(r0, r1);
    lo = *(uint32_t*)&l;
    hi = hu;
}

#define MMA(C, a0, a1, a2, a3, b0, b1)                                        \
    asm volatile("mma.sync.aligned.m16n8k16.row.col.f32.bf16.bf16.f32 "       \
        "{%0,%1,%2,%3}, {%4,%5,%6,%7}, {%8,%9}, {%0,%1,%2,%3};"               \
        : "+f"((C)[0]), "+f"((C)[1]), "+f"((C)[2]), "+f"((C)[3])              \
        : "r"(a0), "r"(a1), "r"(a2), "r"(a3), "r"(b0), "r"(b1))

#define LDSM4(r0, r1, r2, r3, a)                                              \
    asm volatile("ldmatrix.sync.aligned.m8n8.x4.shared.b16 {%0,%1,%2,%3}, [%4];" \
        : "=r"(r0), "=r"(r1), "=r"(r2), "=r"(r3) : "r"(a))
#define LDSM4T(r0, r1, r2, r3, a)                                             \
    asm volatile("ldmatrix.sync.aligned.m8n8.x4.trans.shared.b16 {%0,%1,%2,%3}, [%4];" \
        : "=r"(r0), "=r"(r1), "=r"(r2), "=r"(r3) : "r"(a))

#define BARG(id) asm volatile("bar.sync %0, 128;" :: "r"(id) : "memory")

// ---------------------------------------------------------------------------
// JAX Threefry-2x32, key=[0,42]; partitionable: counter=(0,i), bits=x0^x1,
// keep <=> (bits>>9) < 5872026 (exact integer form of u<0.7f)
// ---------------------------------------------------------------------------
__device__ __forceinline__ uint32_t rotl32(uint32_t x, uint32_t r) {
    return __funnelshift_l(x, x, r);
}
__device__ __forceinline__ bool keep_bit(uint32_t i) {
    const uint32_t ks1 = 42u;
    const uint32_t ks2 = 42u ^ 0x1BD11BDAu;
    uint32_t x0 = 0u, x1 = i + ks1;
#define TF_R(r) { x0 += x1; x1 = rotl32(x1, (r)); x1 ^= x0; }
    TF_R(13) TF_R(15) TF_R(26) TF_R(6)
    x0 += ks1; x1 += ks2 + 1u;
    TF_R(17) TF_R(29) TF_R(16) TF_R(24)
    x0 += ks2; x1 += 2u;
    TF_R(13) TF_R(15) TF_R(26) TF_R(6)
    x1 += ks1 + 3u;
    TF_R(17) TF_R(29) TF_R(16) TF_R(24)
    x0 += ks1; x1 += ks2 + 4u;
    TF_R(13) TF_R(15) TF_R(26) TF_R(6)
    x0 += ks2; x1 += 5u;
#undef TF_R
    return ((x0 ^ x1) >> 9) < 5872026u;
}

// ---------------------------------------------------------------------------
// Two phase-decoupled warp-groups: group g owns k-tiles kt = g, g+2, ...
// Each group: convert K -> GEMM1 -> fixed-max softmax + threefry dropout
// (P register-resident, C-frag == A-frag) -> GEMM2, with group-local
// barriers only. Partial O/l merged through smem at the end (fixed-max
// makes the k-split additive).
// ---------------------------------------------------------------------------
__global__ void __launch_bounds__(NTH, 1)
attn_kernel(const float* __restrict__ x1, const float* __restrict__ x2,
            float* __restrict__ out) {
    extern __shared__ uint32_t smem[];
    uint32_t* QHI = smem;                 // [64][QS]
    uint32_t* QLO = QHI + REG;

    const int tid  = threadIdx.x;
    const int lane = tid & 31;
    const int wid  = tid >> 5;
    const int g    = wid >> 2;            // warp-group 0/1
    const int wl   = wid & 3;             // warp-in-group: q rows [wl*16, wl*16+16)
    const int tidl = tid & 127;
    const int quad = lane & 3;
    const int rowq = lane >> 2;
    const int seg  = lane >> 3;
    const int r8   = lane & 7;
    const int b = blockIdx.y, q0 = blockIdx.x * BQ;

    uint32_t* KHI = QLO + REG + g * (2 * REG);   // group-private K regions
    uint32_t* KLO = KHI + REG;

    const uint32_t aQHI = (uint32_t)__cvta_generic_to_shared(QHI);
    const uint32_t aQLO = (uint32_t)__cvta_generic_to_shared(QLO);
    const uint32_t aKHI = (uint32_t)__cvta_generic_to_shared(KHI);
    const uint32_t aKLO = (uint32_t)__cvta_generic_to_shared(KLO);

    const uint32_t offA  = (uint32_t)((wl * 16 + (seg & 1) * 8 + r8) * QS + (seg >> 1) * 4);
    const uint32_t offB1 = (uint32_t)(((seg >> 1) * 8 + r8) * QS + (seg & 1) * 4);
    const uint32_t offB2 = (uint32_t)(((seg & 1) * 8 + r8) * QS + (seg >> 1) * 4);

    // ---- convert Q once (scale 1.153 folded in), all 256 threads
    const float* gq = x1 + (size_t)(b * NQ + q0) * ND;
#pragma unroll
    for (int it = 0; it < 16; it++) {
        int idx = tid + it * NTH;
        int row = idx >> 6, cp = idx & 63;
        float2 v = *(const float2*)(gq + row * ND + 2 * cp);
        uint32_t hi, lo;
        split2(v.x * 1.153f, v.y * 1.153f, hi, lo);
        QHI[row * QS + cp] = hi;
        QLO[row * QS + cp] = lo;
    }
    __syncthreads();                      // Q ready for both groups

    float On[16][4];
#pragma unroll
    for (int dn = 0; dn < 16; dn++)
#pragma unroll
        for (int c = 0; c < 4; c++) On[dn][c] = 0.0f;
    float lp0 = 0.0f, lp1 = 0.0f;

    const uint32_t rb0 = (uint32_t)(b * NQ + q0 + wl * 16 + rowq) * (uint32_t)NK;
    const uint32_t rb1 = rb0 + 8u * (uint32_t)NK;
    const float* gk0 = x2 + (size_t)b * NK * ND;
    const int barid = 1 + g;

    for (int kt = g; kt < NK / BK; kt += 2) {
        const float* gk = gk0 + (size_t)(kt * BK) * ND;

        // ---- convert K tile (group-local, 128 threads)
#pragma unroll
        for (int it = 0; it < 32; it++) {
            int idx = tidl + it * 128;
            int kr = idx >> 6, cp = idx & 63;
            float2 v = *(const float2*)(gk + kr * ND + 2 * cp);
            uint32_t hi, lo;
            split2(v.x, v.y, hi, lo);
            KHI[kr * QS + cp] = hi;
            KLO[kr * QS + cp] = lo;
        }
        BARG(barid);                      // K tile ready within group

        // ---- GEMM1: C[8 ntiles][4] = Qs @ K^T (3 split products)
        float C[8][4];
#pragma unroll
        for (int n = 0; n < 8; n++)
#pragma unroll
            for (int c = 0; c < 4; c++) C[n][c] = 0.0f;

#pragma unroll
        for (int dc = 0; dc < 8; dc++) {
            uint32_t ah0, ah1, ah2, ah3, al0, al1, al2, al3;
            LDSM4(ah0, ah1, ah2, ah3, aQHI + (offA + dc * 8) * 4);
            LDSM4(al0, al1, al2, al3, aQLO + (offA + dc * 8) * 4);
#pragma unroll
            for (int np = 0; np < 4; np++) {
                uint32_t d1 = (offB1 + (uint32_t)(np * 16) * QS + dc * 8) * 4;
                uint32_t bh0, bh1, bh2, bh3, bl0, bl1, bl2, bl3;
                LDSM4(bh0, bh1, bh2, bh3, aKHI + d1);
                LDSM4(bl0, bl1, bl2, bl3, aKLO + d1);
                MMA(C[2 * np],     ah0, ah1, ah2, ah3, bh0, bh1);
                MMA(C[2 * np],     ah0, ah1, ah2, ah3, bl0, bl1);
                MMA(C[2 * np],     al0, al1, al2, al3, bh0, bh1);
                MMA(C[2 * np + 1], ah0, ah1, ah2, ah3, bh2, bh3);
                MMA(C[2 * np + 1], ah0, ah1, ah2, ah3, bl2, bl3);
                MMA(C[2 * np + 1], al0, al1, al2, al3, bh2, bh3);
            }
        }

        // ---- fixed-max softmax + threefry dropout, pack P into A-frags
        uint32_t phi[4][4], plo[4][4];
#pragma unroll
        for (int n = 0; n < 8; n++) {
            uint32_t kg = (uint32_t)(kt * BK + n * 8 + 2 * quad);
            float e0 = __expf(C[n][0]);
            float e1 = __expf(C[n][1]);
            float e2 = __expf(C[n][2]);
            float e3 = __expf(C[n][3]);
            lp0 += e0 + e1;               // unmasked denominator
            lp1 += e2 + e3;
            float p00 = keep_bit(rb0 + kg)      ? e0 : 0.0f;
            float p01 = keep_bit(rb0 + kg + 1u) ? e1 : 0.0f;
            float p10 = keep_bit(rb1 + kg)      ? e2 : 0.0f;
            float p11 = keep_bit(rb1 + kg + 1u) ? e3 : 0.0f;
            int kc = n >> 1;
            if ((n & 1) == 0) {
                split2(p00, p01, phi[kc][0], plo[kc][0]);
                split2(p10, p11, phi[kc][1], plo[kc][1]);
            } else {
                split2(p00, p01, phi[kc][2], plo[kc][2]);
                split2(p10, p11, phi[kc][3], plo[kc][3]);
            }
        }

        // ---- GEMM2: On += P @ V; V-frags via ldmatrix.trans from K buffers
#pragma unroll
        for (int kc = 0; kc < 4; kc++) {
#pragma unroll
            for (int dnp = 0; dnp < 8; dnp++) {
                uint32_t d2 = (offB2 + (uint32_t)(kc * 16) * QS + dnp * 8) * 4;
                uint32_t vh0, vh1, vh2, vh3, vl0, vl1, vl2, vl3;
                LDSM4T(vh0, vh1, vh2, vh3, aKHI + d2);
                LDSM4T(vl0, vl1, vl2, vl3, aKLO + d2);
                MMA(On[2 * dnp], phi[kc][0], phi[kc][1], phi[kc][2], phi[kc][3], vh0, vh1);
                MMA(On[2 * dnp], phi[kc][0], phi[kc][1], phi[kc][2], phi[kc][3], vl0, vl1);
                MMA(On[2 * dnp], plo[kc][0], plo[kc][1], plo[kc][2], plo[kc][3], vh0, vh1);
                MMA(On[2 * dnp + 1], phi[kc][0], phi[kc][1], phi[kc][2], phi[kc][3], vh2, vh3);
                MMA(On[2 * dnp + 1], phi[kc][0], phi[kc][1], phi[kc][2], phi[kc][3], vl2, vl3);
                MMA(On[2 * dnp + 1], plo[kc][0], plo[kc][1], plo[kc][2], plo[kc][3], vh2, vh3);
            }
        }
        BARG(barid);                      // GEMM2 done before next K overwrite
    }

    // ---- reduce l over quad lanes
    lp0 += __shfl_xor_sync(0xffffffffu, lp0, 1);
    lp0 += __shfl_xor_sync(0xffffffffu, lp0, 2);
    lp1 += __shfl_xor_sync(0xffffffffu, lp1, 1);
    lp1 += __shfl_xor_sync(0xffffffffu, lp1, 2);

    // ---- merge the two groups' partial O and l
    float* sL = (float*)(smem + 6 * REG);       // [2][64]
    float* MB = (float*)(smem + 2 * REG);       // merge buffer [64][128] (group-0 K region)
    __syncthreads();                            // both groups done computing
    if (quad == 0) {
        sL[g * 64 + wl * 16 + rowq]     = lp0;
        sL[g * 64 + wl * 16 + rowq + 8] = lp1;
    }
    if (g == 0) {
        int r0 = wl * 16 + rowq;
#pragma unroll
        for (int dn = 0; dn < 16; dn++) {
            int col = dn * 8 + 2 * quad;
            MB[r0 * 128 + col]           = On[dn][0];
            MB[r0 * 128 + col + 1]       = On[dn][1];
            MB[(r0 + 8) * 128 + col]     = On[dn][2];
            MB[(r0 + 8) * 128 + col + 1] = On[dn][3];
        }
    }
    __syncthreads();
    if (g == 1) {
        int r0 = wl * 16 + rowq;
        float inv0 = 1.0f / (0.7f * (sL[r0]     + sL[64 + r0]));
        float inv1 = 1.0f / (0.7f * (sL[r0 + 8] + sL[64 + r0 + 8]));
        float* g0p = out + (size_t)(b * NQ + q0 + r0) * ND + 2 * quad;
        float* g1p = g0p + 8 * ND;
#pragma unroll
        for (int dn = 0; dn < 16; dn++) {
            int col = dn * 8 + 2 * quad;
            float2 s0, s1;
            s0.x = (On[dn][0] + MB[r0 * 128 + col])           * inv0;
            s0.y = (On[dn][1] + MB[r0 * 128 + col + 1])       * inv0;
            s1.x = (On[dn][2] + MB[(r0 + 8) * 128 + col])     * inv1;
            s1.y = (On[dn][3] + MB[(r0 + 8) * 128 + col + 1]) * inv1;
            *(float2*)(g0p + dn * 8) = s0;
            *(float2*)(g1p + dn * 8) = s1;
        }
    }
}

// ---------------------------------------------------------------------------
extern "C" void kernel_launch(void* const* d_in, const int* in_sizes, int n_in,
                              void* d_out, int out_size) {
    const float* x1 = (const float*)d_in[0];
    const float* x2 = (const float*)d_in[1];
    float* out = (float*)d_out;

    size_t smem = (size_t)SMEM_U32 * 4;   // 104,960 B
    cudaFuncSetAttribute(attn_kernel,
                         cudaFuncAttributeMaxDynamicSharedMemorySize, (int)smem);
    dim3 grid(NQ / BQ, NB);
    attn_kernel<<<grid, NTH, smem>>>(x1, x2, out);
}